// round 9
// baseline (speedup 1.0000x reference)
#include <cuda_runtime.h>
#include <cuda_bf16.h>
#include <cuda_fp16.h>

// 8-row strip per 64-thread block; warp 0 streams pixel rows y0-1..y0+3,
// warp 1 streams y0+4..y0+8 (5 rows each). Seam partials (out rows y0+3,
// y0+4) exchanged via smem -> halo factor 10/8 instead of 12/8.
__global__ __launch_bounds__(64, 16)
void kan_conv_kernel(const float* __restrict__ x,
                     const float* __restrict__ bw,
                     const float* __restrict__ sw,
                     const float* __restrict__ ss,
                     float* __restrict__ out)
{
    __shared__ uint2  polyH[12 * 9];  // [cell j][feature f] = {h2(a0,a1), h2(a2,a3)}; j=11 zero
    __shared__ float  Zs[9];          // spline value at padding pixels (x=0)
    __shared__ float2 xbuf[2][32];    // seam partials: [0]=warp0's y0+4, [1]=warp1's y0+3

    const int lane  = threadIdx.x & 31;
    const int warp  = threadIdx.x >> 5;
    const int img   = blockIdx.x >> 3;      // 2048 blocks = 256 images x 8 strips
    const int strip = blockIdx.x & 7;
    const int y0    = strip * 8;

    // ---- build polynomial table (scaled spline weights -> fp16 cubic coeffs) ----
    // a0=(W0+4W1+W2)/6, a1=(W2-W0)/2, a2=(W0-2W1+W2)/2, a3=(W3-W0+3(W1-W2))/6
    for (int t = threadIdx.x; t < 108; t += 64) {
        const int j = t / 9, f = t - j * 9;
        float a0 = 0.f, a1 = 0.f, a2 = 0.f, a3 = 0.f;
        if (j < 11) {
            float scale = __ldg(&ss[f]);
            float W[4];
            #pragma unroll
            for (int c = 0; c < 4; c++) {
                int bi = j + c - 3;
                W[c] = (bi >= 0 && bi < 8) ? __ldg(&sw[f * 8 + bi]) * scale : 0.f;
            }
            const float S = 1.f / 6.f;
            a0 = (W[0] + 4.f * W[1] + W[2]) * S;
            a1 = (W[2] - W[0]) * 0.5f;
            a2 = (W[0] - 2.f * W[1] + W[2]) * 0.5f;
            a3 = (W[3] - W[0] + 3.f * (W[1] - W[2])) * S;
        }
        __half2 h01 = __floats2half2_rn(a0, a1);
        __half2 h23 = __floats2half2_rn(a2, a3);
        uint2 e;
        e.x = *reinterpret_cast<unsigned*>(&h01);
        e.y = *reinterpret_cast<unsigned*>(&h23);
        polyH[t] = e;
        // padding pixel value: x=0 -> cell j=5, u=0.5, silu=0 (fp32 exact)
        if (j == 5) Zs[f] = fmaf(fmaf(fmaf(a3, 0.5f, a2), 0.5f, a1), 0.5f, a0);
    }
    float bwr[9];
    #pragma unroll
    for (int f = 0; f < 9; f++) bwr[f] = __ldg(&bw[f]);
    __syncthreads();

    float Z[9];
    #pragma unroll
    for (int f = 0; f < 9; f++) Z[f] = Zs[f];

    const float* xcol = x   + img * 4096 + lane * 2;
    float*       ocol = out + img * 4096 + lane * 2;

    float accE[3] = {0.f, 0.f, 0.f};
    float accO[3] = {0.f, 0.f, 0.f};
    float holdE = 0.f, holdO = 0.f;     // warp1's y0+4 partial

    auto evalf = [&](int jbase, float u, float s, int f) {
        uint2 pk = polyH[jbase + f];
        float2 c01 = __half22float2(*reinterpret_cast<__half2*>(&pk.x));
        float2 c23 = __half22float2(*reinterpret_cast<__half2*>(&pk.y));
        float t = fmaf(c23.y, u, c23.x);
        t = fmaf(t, u, c01.y);
        t = fmaf(t, u, c01.x);
        return fmaf(s, bwr[f], t);
    };

    const int py0 = y0 - 1 + warp * 5;  // warp0: y0-1.. ; warp1: y0+4..

    #pragma unroll
    for (int r = 0; r < 5; r++) {
        const int py = py0 + r;
        float2 p = make_float2(0.f, 0.f);           // zero padding outside image
        if (py >= 0 && py < 64) p = *(const float2*)(xcol + py * 64);

        const float ve = p.x, vo = p.y;
        const float se = ve * __frcp_rn(1.f + __expf(-ve));
        const float so = vo * __frcp_rn(1.f + __expf(-vo));

        float xce = fmaf(ve, 2.5f, 5.5f);           // (v+2.2)/0.4
        float jfe = floorf(xce);
        float ue  = xce - jfe;
        int   je  = (int)jfe;
        if ((unsigned)je > 10u) { je = 11; ue = 0.f; }   // zero row of table

        float xco = fmaf(vo, 2.5f, 5.5f);
        float jfo = floorf(xco);
        float uo  = xco - jfo;
        int   jo  = (int)jfo;
        if ((unsigned)jo > 10u) { jo = 11; uo = 0.f; }

        const int jbe = je * 9;
        const int jbo = jo * 9;

        // pixel col c serves out col c+1 (kw=0), c (kw=1), c-1 (kw=2);
        // pixel row py with kh serves out row py+1-kh -> slot [2-kh].
        float sendL[3], sendR[3];
        #pragma unroll
        for (int kh = 0; kh < 3; kh++) {
            accO[2 - kh] += evalf(jbe, ue, se, kh * 3 + 0);
            accE[2 - kh] += evalf(jbe, ue, se, kh * 3 + 1);
            sendL[kh]     = evalf(jbe, ue, se, kh * 3 + 2);
            sendR[kh]     = evalf(jbo, uo, so, kh * 3 + 0);
            accO[2 - kh] += evalf(jbo, uo, so, kh * 3 + 1);
            accE[2 - kh] += evalf(jbo, uo, so, kh * 3 + 2);
        }
        #pragma unroll
        for (int kh = 0; kh < 3; kh++) {
            float rl = __shfl_down_sync(0xffffffffu, sendL[kh], 1);
            if (lane == 31) rl = Z[kh * 3 + 2];     // col 64 padding -> out col 63
            float rr = __shfl_up_sync(0xffffffffu, sendR[kh], 1);
            if (lane == 0)  rr = Z[kh * 3 + 0];     // col -1 padding -> out col 0
            accO[2 - kh] += rl;
            accE[2 - kh] += rr;
        }

        // retire acc slot 0 (out row py-1)
        if (warp == 0) {
            if (r >= 2)                              // rows y0, y0+1, y0+2
                *(float2*)(ocol + (y0 + r - 2) * 64) = make_float2(accE[0], accO[0]);
        } else {
            if (r == 0) {                            // partial of out row y0+3 (from py=y0+4)
                xbuf[1][lane] = make_float2(accE[0], accO[0]);
            } else if (r == 1) {                     // partial of out row y0+4 (missing py=y0+3)
                holdE = accE[0]; holdO = accO[0];
            } else {                                 // rows y0+5, y0+6, y0+7
                *(float2*)(ocol + (y0 + 3 + r) * 64) = make_float2(accE[0], accO[0]);
            }
        }
        accE[0] = accE[1]; accE[1] = accE[2]; accE[2] = 0.f;
        accO[0] = accO[1]; accO[1] = accO[2]; accO[2] = 0.f;
    }

    // warp0 post-loop: acc[0] = partial y0+3 (missing py=y0+4),
    //                  acc[1] = partial y0+4 (only py=y0+3 contribution)
    if (warp == 0) xbuf[0][lane] = make_float2(accE[1], accO[1]);
    __syncthreads();

    if (warp == 0) {
        float2 q = xbuf[1][lane];
        *(float2*)(ocol + (y0 + 3) * 64) = make_float2(accE[0] + q.x, accO[0] + q.y);
    } else {
        float2 q = xbuf[0][lane];
        *(float2*)(ocol + (y0 + 4) * 64) = make_float2(holdE + q.x, holdO + q.y);
    }
}

extern "C" void kernel_launch(void* const* d_in, const int* in_sizes, int n_in,
                              void* d_out, int out_size) {
    const float* x  = (const float*)d_in[0];  // (8,32,64,64)
    const float* bw = (const float*)d_in[1];  // (1,9)
    const float* sw = (const float*)d_in[2];  // (1,9,8)
    const float* ss = (const float*)d_in[3];  // (1,9)
    float* out = (float*)d_out;

    // 256 images x 8 strips; 2-warp team per strip
    kan_conv_kernel<<<2048, 64>>>(x, bw, sw, ss, out);
}